// round 17
// baseline (speedup 1.0000x reference)
#include <cuda_runtime.h>
#include <cuda_bf16.h>
#include <cstdint>

#define NB 64
#define LL 200
#define DD 300
#define DP 320
#define PP 16
#define EPSV 1e-12f
#define KC 32            // 2 k16 steps per chunk
#define NCH 10
#define NT_THREADS 416   // 13 warps

#define RSB 80           // row stride bytes (32 bf16 = 64B + 16B pad, conflict-free)
#define A_PLANE 16640    // 208 * 80
#define A_BUFST 33280    // hi+lo
#define IB 104           // i rows staged per CTA (100 valid)
#define B_PLANE 8320     // 104 * 80
#define B_BUFST 16640

#define SM_WSQ   0                    // 320 floats
#define SM_INV2  1280                 // 208 floats
#define SM_A     2112                 // 2 bufs x (hi|lo)
#define SM_B     (SM_A + 2*A_BUFST)   // 68672
#define SM_WRED  SM_A                 // aliased: used only after mainloop
#define SM_TOTAL (SM_B + 2*B_BUFST)   // 101952 -> 2 CTAs/SM

__device__ float g_inv_n1[NB*LL*PP];
__device__ float g_inv_n2[NB*LL*PP];
__device__ unsigned short g_s2h[(size_t)NB*LL*DP];
__device__ unsigned short g_s2l[(size_t)NB*LL*DP];

// ---------------- PTX helpers ----------------
__device__ __forceinline__ unsigned smem_u32(const void* p) {
    unsigned a;
    asm("{ .reg .u64 t; cvta.to.shared.u64 t, %1; cvt.u32.u64 %0, t; }"
        : "=r"(a) : "l"(p));
    return a;
}

#define CP16(dst, src) \
    asm volatile("cp.async.cg.shared.global [%0], [%1], 16;" \
                 :: "r"(dst), "l"(src) : "memory")
#define CP_COMMIT() asm volatile("cp.async.commit_group;" ::: "memory")
#define CP_WAIT(n)  asm volatile("cp.async.wait_group %0;" :: "n"(n) : "memory")

#define LDSM4(r, a) \
    asm volatile("ldmatrix.sync.aligned.m8n8.x4.shared.b16 {%0,%1,%2,%3}, [%4];" \
        : "=r"((r)[0]),"=r"((r)[1]),"=r"((r)[2]),"=r"((r)[3]) : "r"(a))
#define LDSM2(r, a) \
    asm volatile("ldmatrix.sync.aligned.m8n8.x2.shared.b16 {%0,%1}, [%2];" \
        : "=r"((r)[0]),"=r"((r)[1]) : "r"(a))

#define MMA(c, a, b) \
    asm volatile("mma.sync.aligned.m16n8k16.row.col.f32.bf16.bf16.f32 " \
        "{%0,%1,%2,%3}, {%4,%5,%6,%7}, {%8,%9}, {%0,%1,%2,%3};" \
        : "+f"((c)[0]),"+f"((c)[1]),"+f"((c)[2]),"+f"((c)[3]) \
        : "r"((a)[0]),"r"((a)[1]),"r"((a)[2]),"r"((a)[3]), \
          "r"((b)[0]),"r"((b)[1]))

// packed split: (f0,f1) -> hi bf16x2 bits, lo bf16x2 bits (lo = f - float(hi))
__device__ __forceinline__ void split_pair(float f0, float f1,
                                           unsigned& hu, unsigned& lu) {
    __nv_bfloat162 h = __float22bfloat162_rn(make_float2(f0, f1));
    float2 hf = __bfloat1622float2(h);
    __nv_bfloat162 l = __float22bfloat162_rn(make_float2(f0 - hf.x, f1 - hf.y));
    hu = *(unsigned*)&h;
    lu = *(unsigned*)&l;
}

// ---------------------------------------------------------------------------
// norms v5: one row per warp; block 512 = 8 s1-rows + 8 s2-rows; grid 1600.
// inv_n[row][p] = rsqrt(max(sum_d s[row,d]^2 * k[p,d]^2, eps))
// ---------------------------------------------------------------------------
__global__ void __launch_bounds__(512)
norms_kernel(const float* __restrict__ s1, const float* __restrict__ s2,
             const float* __restrict__ kern) {
    __shared__ float wsh[PP * DD + 32];
    int tid = threadIdx.x;
    for (int e = tid; e < PP * DD; e += 512) {
        float k = kern[e];
        wsh[e] = k * k;
    }
    if (tid < 32) wsh[PP * DD + tid] = 0.f;
    __syncthreads();

    int lane = tid & 31, w = tid >> 5;
    int row = blockIdx.x * 8 + (w & 7);
    const float* src = (w < 8) ? s1 : s2;
    float* dst       = (w < 8) ? g_inv_n1 : g_inv_n2;

    float sq[10];
    const float* srow = src + (size_t)row * DD;
#pragma unroll
    for (int k = 0; k < 10; k++) {
        int d = lane + 32 * k;
        float v = (d < DD) ? srow[d] : 0.f;
        sq[k] = v * v;
    }

#pragma unroll
    for (int p = 0; p < PP; p++) {
        float a = 0.f;
#pragma unroll
        for (int k = 0; k < 10; k++)
            a += sq[k] * wsh[p * DD + lane + 32 * k];   // sq==0 where d>=DD
        a += __shfl_xor_sync(0xffffffffu, a, 1);
        a += __shfl_xor_sync(0xffffffffu, a, 2);
        a += __shfl_xor_sync(0xffffffffu, a, 4);
        a += __shfl_xor_sync(0xffffffffu, a, 8);
        a += __shfl_xor_sync(0xffffffffu, a, 16);
        if (lane == 0)
            dst[row * PP + p] = rsqrtf(fmaxf(a, EPSV));
    }
}

// ---------------------------------------------------------------------------
// split2 v3: s2 -> bf16 hi/lo, K padded to 320; 8 elems/thread.
// block 320 = 8 rows x 40 groups; grid NB*LL/8 = 1600.
// ---------------------------------------------------------------------------
__global__ void __launch_bounds__(320)
split2_kernel(const float* __restrict__ s2) {
    int t = threadIdx.x;
    int r = t / 40;
    int g = t - r * 40;
    int row = blockIdx.x * 8 + r;
    int d = g * 8;
    float4 v0 = make_float4(0.f, 0.f, 0.f, 0.f);
    float4 v1 = make_float4(0.f, 0.f, 0.f, 0.f);
    const float* srow = s2 + (size_t)row * DD;
    if (d < DD)     v0 = *(const float4*)(srow + d);
    if (d + 4 < DD) v1 = *(const float4*)(srow + d + 4);
    unsigned h0, l0, h1, l1, h2, l2, h3, l3;
    split_pair(v0.x, v0.y, h0, l0);
    split_pair(v0.z, v0.w, h1, l1);
    split_pair(v1.x, v1.y, h2, l2);
    split_pair(v1.z, v1.w, h3, l3);
    size_t off = (size_t)row * DP + d;
    *(uint4*)(g_s2h + off) = make_uint4(h0, h1, h2, h3);
    *(uint4*)(g_s2l + off) = make_uint4(l0, l1, l2, l3);
}

// ---------------------------------------------------------------------------
// stage A chunk (j-side = s2 split, 208 rows x 32): cp.async 16B, 2 its
// ---------------------------------------------------------------------------
__device__ __forceinline__ void stageA(unsigned aHb, int b, int c, int tid) {
#pragma unroll
    for (int it = 0; it < 2; it++) {
        int e = tid + it * NT_THREADS;       // 0..831 (208*4)
        int r = e >> 2, sub = e & 3;
        int j = (r < LL) ? r : (LL - 1);
        size_t g = ((size_t)(b * LL + j)) * DP + c * KC + sub * 8;
        unsigned dst = aHb + r * RSB + sub * 16;
        CP16(dst, g_s2h + g);
        CP16(dst + A_PLANE, g_s2l + g);
    }
}

// ---------------------------------------------------------------------------
// stage B chunk (i-side = s1 * w^2, 104 rows x 32, rows>=100 zero)
// ---------------------------------------------------------------------------
__device__ __forceinline__ void stageB(unsigned bHb, const float* __restrict__ s1,
                                       const float* __restrict__ wsq,
                                       int b, int bx, int c, int tid) {
#pragma unroll
    for (int it = 0; it < 2; it++) {
        int e = tid + it * NT_THREADS;       // 0..831 (104*8)
        int r = e >> 3, g = e & 7;
        int d = c * KC + g * 4;
        float4 v = make_float4(0.f, 0.f, 0.f, 0.f);
        if (d < DD && r < 100)
            v = *(const float4*)(s1 + ((size_t)(b * LL + bx * 100 + r)) * DD + d);
        float4 w = *(const float4*)(wsq + d);
        unsigned hu0, lu0, hu1, lu1;
        split_pair(v.x * w.x, v.y * w.y, hu0, lu0);
        split_pair(v.z * w.z, v.w * w.w, hu1, lu1);
        unsigned dst = bHb + r * RSB + g * 8;
        asm volatile("st.shared.v2.b32 [%0], {%1, %2};" :: "r"(dst), "r"(hu0), "r"(hu1) : "memory");
        asm volatile("st.shared.v2.b32 [%0], {%1, %2};" :: "r"(dst + B_PLANE), "r"(lu0), "r"(lu1) : "memory");
    }
}

// ---------------------------------------------------------------------------
// Main kernel: grid (2 i-halves, 16 p, 64 b), 416 threads (13 warps), occ 2.
// M = j (208, 13 m16-tiles, one per warp), N = i (104, 13 n8-tiles), K = 320.
// ---------------------------------------------------------------------------
__global__ void __launch_bounds__(NT_THREADS, 2)
mm_kernel(const float* __restrict__ s1, const float* __restrict__ s2,
          const float* __restrict__ kern, float* __restrict__ out) {
    extern __shared__ __align__(16) char smem[];
    unsigned sb = smem_u32(smem);
    float* wsq   = (float*)(smem + SM_WSQ);
    float* inv2s = (float*)(smem + SM_INV2);
    float* wred  = (float*)(smem + SM_WRED);   // aliases A tiles (dead after mainloop)

    int tid = threadIdx.x;
    int lane = tid & 31, wid = tid >> 5;
    int bx = blockIdx.x, p = blockIdx.y, b = blockIdx.z;

    for (int e = tid; e < DP; e += NT_THREADS) {
        float k = (e < DD) ? kern[p * DD + e] : 0.f;
        wsq[e] = k * k;
    }
    for (int e = tid; e < 208; e += NT_THREADS) {
        int j = (e < LL) ? e : (LL - 1);
        inv2s[e] = g_inv_n2[(b * LL + j) * PP + p];
    }
    __syncthreads();

    float acc[13][4];
#pragma unroll
    for (int nt = 0; nt < 13; nt++)
#pragma unroll
        for (int q = 0; q < 4; q++) acc[nt][q] = 0.f;

    unsigned a_off = (unsigned)((wid * 16 + (lane & 15)) * RSB + ((lane >> 4) << 4));
    unsigned b_off4 = (unsigned)(((lane & 7) + ((lane >> 4) << 3)) * RSB + (((lane >> 3) & 1) << 4));
    unsigned b_off2 = (unsigned)((lane & 7) * RSB + (((lane >> 3) & 1) << 4));

    // prologue: chunk 0 -> buf 0
    stageA(sb + SM_A, b, 0, tid);
    stageB(sb + SM_B, s1, wsq, b, bx, 0, tid);
    CP_COMMIT();

    for (int c = 0; c < NCH; c++) {
        if (c + 1 < NCH) {
            int nb = (c + 1) & 1;
            stageA(sb + SM_A + nb * A_BUFST, b, c + 1, tid);
            stageB(sb + SM_B + nb * B_BUFST, s1, wsq, b, bx, c + 1, tid);
            CP_COMMIT();
            CP_WAIT(1);
        } else {
            CP_WAIT(0);
        }
        __syncthreads();     // chunk c fully staged

        unsigned aH = sb + SM_A + (c & 1) * A_BUFST;
        unsigned bH = sb + SM_B + (c & 1) * B_BUFST;
        unsigned ah[4], al[4], bh[4], bl[4];
#pragma unroll
        for (int ks = 0; ks < 2; ks++) {
            unsigned aaddr = aH + a_off + ks * 32;
            LDSM4(ah, aaddr);
            LDSM4(al, aaddr + A_PLANE);
#pragma unroll
            for (int t2 = 0; t2 < 6; t2++) {
                int nt = t2 * 2;
                unsigned baddr = bH + b_off4 + t2 * (16 * RSB) + ks * 32;
                LDSM4(bh, baddr);
                LDSM4(bl, baddr + B_PLANE);
                MMA(acc[nt], ah, bh);
                MMA(acc[nt], ah, bl);
                MMA(acc[nt], al, bh);
                MMA(acc[nt + 1], ah, bh + 2);
                MMA(acc[nt + 1], ah, bl + 2);
                MMA(acc[nt + 1], al, bh + 2);
            }
            unsigned baddr = bH + b_off2 + 12 * (8 * RSB) + ks * 32;
            LDSM2(bh, baddr);
            LDSM2(bl, baddr + B_PLANE);
            MMA(acc[12], ah, bh);
            MMA(acc[12], ah, bl);
            MMA(acc[12], al, bh);
        }
        __syncthreads();     // all warps done reading buf (c&1)
    }

    // ---- epilogue: scale by inv_n2[j], max over j ----
    float invA = inv2s[wid * 16 + (lane >> 2)];
    float invB = inv2s[wid * 16 + (lane >> 2) + 8];
#pragma unroll
    for (int nt = 0; nt < 13; nt++) {
        float v0 = fmaxf(acc[nt][0] * invA, acc[nt][2] * invB);
        float v1 = fmaxf(acc[nt][1] * invA, acc[nt][3] * invB);
        v0 = fmaxf(v0, __shfl_xor_sync(0xffffffffu, v0, 4));
        v0 = fmaxf(v0, __shfl_xor_sync(0xffffffffu, v0, 8));
        v0 = fmaxf(v0, __shfl_xor_sync(0xffffffffu, v0, 16));
        v1 = fmaxf(v1, __shfl_xor_sync(0xffffffffu, v1, 4));
        v1 = fmaxf(v1, __shfl_xor_sync(0xffffffffu, v1, 8));
        v1 = fmaxf(v1, __shfl_xor_sync(0xffffffffu, v1, 16));
        if (lane < 4) {
            wred[wid * IB + nt * 8 + 2 * lane]     = v0;
            wred[wid * IB + nt * 8 + 2 * lane + 1] = v1;
        }
    }
    __syncthreads();

    if (tid < 100) {
        float m = wred[tid];
#pragma unroll
        for (int w = 1; w < 13; w++) m = fmaxf(m, wred[w * IB + tid]);
        int ig = bx * 100 + tid;
        out[((size_t)(b * LL + ig)) * PP + p] = m * g_inv_n1[(b * LL + ig) * PP + p];
    }
}

// ---------------------------------------------------------------------------
extern "C" void kernel_launch(void* const* d_in, const int* in_sizes, int n_in,
                              void* d_out, int out_size) {
    const float* s1   = (const float*)d_in[0];   // (64,200,300)
    const float* s2   = (const float*)d_in[1];   // (64,200,300)
    const float* kern = (const float*)d_in[2];   // (16,300)
    float* out = (float*)d_out;                  // (64,200,16)

    cudaFuncSetAttribute(mm_kernel, cudaFuncAttributeMaxDynamicSharedMemorySize,
                         SM_TOTAL);

    norms_kernel<<<NB * LL / 8, 512>>>(s1, s2, kern);
    split2_kernel<<<NB * LL / 8, 320>>>(s2);
    mm_kernel<<<dim3(2, PP, NB), NT_THREADS, SM_TOTAL>>>(s1, s2, kern, out);
}